// round 11
// baseline (speedup 1.0000x reference)
#include <cuda_runtime.h>
#include <cuda_fp16.h>

// Problem constants
#define NC     5
#define NB     128000
#define BATCH  8
#define NJ     15
#define HH     128
#define WW     240
#define HMPIX  (HH*WW)        // 30720 pixels per (b,cam,j) heatmap

// Warp-specialized CTA: 1024 threads = 25 consumer warps (800 thr, gather
// only) + 7 producer warps (224 thr, fill only). Double-buffered u8-pair
// heatmaps (2 x 61,920 B = 123,840 B smem -> 1 CTA/SM).
#define THREADS   1024
#define CTHREADS  800        // consumer threads (25 warps)
#define PTHREADS  224        // producer threads (7 warps)
#define BPT       32         // bins per consumer thread: 800*32 = 25600
#define CHUNK     25600
#define NCHUNK    (NB/CHUNK) // 5 chunks -> grid 5 x 15 x 8 = 600 CTAs
#define SPAIRS    (HMPIX + WW)  // u16 pairs incl. zero pad row = 30960
#define PFILL_IT  35         // ceil(7680/224); boundary 64 thr = warp-uniform

// Named barriers: 1,2 = buffer full (producers arrive, consumers sync);
//                 3,4 = buffer free (consumers arrive, producers sync).
#define BAR_SYNC(id)   asm volatile("bar.sync %0, 1024;"   :: "r"(id) : "memory")
#define BAR_ARRIVE(id) asm volatile("bar.arrive %0, 1024;" :: "r"(id) : "memory")

// Fused 8-byte per-(cam,bin) record (shared across all b,j):
//   .x = off (bits 0..15) | t_half_bits (bits 16..31)
//   .y = half2(vA, vB)  -- x-weights with border cases and the u8 scale
//                          (1/255) folded in.
// Gather on a u8-pair heatmap buffer su[] (2 bytes per pixel):
//   su[p] = (q[y][x], q[y][x+1]), q = round(255*hm); col x+1 OOB -> 0;
//   row HH is a zero pad row (handles y1 OOB).
//   p0 = su[off] (row y0), p1 = su[off+WW] (row y0+1)
//   result = (vA,vB) . ( p0 + t*(p1-p0) )
__device__ uint2 g_rec[NC*NB];

__device__ __forceinline__ uint2 make_record(float gx, float gy) {
    // align_corners=True mapping
    float ix = (gx + 1.0f) * 0.5f * (float)(WW - 1);
    float iy = (gy + 1.0f) * 0.5f * (float)(HH - 1);
    float x0f = floorf(ix), y0f = floorf(iy);
    float fx = ix - x0f,    fy = iy - y0f;
    int   x0 = (int)x0f,    y0 = (int)y0f;

    float wA, wB; int xc;
    if (x0 >= 0 && x0 < WW) { xc = x0; wA = 1.0f - fx; wB = fx;  }
    else if (x0 == -1)      { xc = 0;  wA = fx;        wB = 0.f; }
    else                    { xc = 0;  wA = 0.f;       wB = 0.f; }

    float t, s; int yc;
    if (y0 >= 0 && y0 < HH) { yc = y0; t = fy;  s = 1.f; }
    else if (y0 == -1)      { yc = 0;  t = 0.f; s = fy;  }
    else                    { yc = 0;  t = 0.f; s = 0.f; }

    unsigned int off = (unsigned int)(yc * WW + xc);   // <= 30719
    __half th = __float2half_rn(t);
    const float inv255 = 1.0f / 255.0f;
    __half2 v = __floats2half2_rn(wA * s * inv255, wB * s * inv255);

    uint2 r;
    r.x = off | ((unsigned int)__half_as_ushort(th) << 16);
    r.y = *reinterpret_cast<unsigned int*>(&v);
    return r;
}

__global__ void prep_kernel(const float* __restrict__ grid) {
    int p = blockIdx.x * 256 + threadIdx.x;   // record pair index
    if (p >= NC * NB / 2) return;
    float4 g = reinterpret_cast<const float4*>(grid)[p];
    g_rec[p * 2]     = make_record(g.x, g.y);
    g_rec[p * 2 + 1] = make_record(g.z, g.w);
}

__device__ __forceinline__ unsigned int pack_u8x4(float4 v) {
    unsigned int q0 = __float2uint_rn(v.x * 255.f);
    unsigned int q1 = __float2uint_rn(v.y * 255.f);
    unsigned int q2 = __float2uint_rn(v.z * 255.f);
    unsigned int q3 = __float2uint_rn(v.w * 255.f);
    return q0 | (q1 << 8) | (q2 << 16) | (q3 << 24);
}

__global__ __launch_bounds__(THREADS, 1)
void sample_kernel(const float* __restrict__ heatmaps,
                   float* __restrict__ out) {
    // Two u8-pair heatmap buffers, 30960 u16 each.
    extern __shared__ unsigned short su[];

    const int tid   = threadIdx.x;
    const int chunk = blockIdx.x;
    const int j     = blockIdx.y;
    const int b     = blockIdx.z;
    const int base  = chunk * CHUNK;

    // Zero both buffers' pad rows once (all threads), then one full barrier.
    if (tid < WW) { su[HMPIX + tid] = 0; su[SPAIRS + HMPIX + tid] = 0; }
    __syncthreads();

    const float* hmbase = heatmaps + (((size_t)b * NC) * NJ + j) * (size_t)HMPIX;
    const size_t camstride = (size_t)NJ * HMPIX;

    if (tid >= CTHREADS) {
        // ---------------- PRODUCER warps (7): fill only ----------------
        const int ptid   = tid - CTHREADS;            // 0..223
        const bool lane31 = ((ptid & 31) == 31);
        // x of this thread's float4's first pixel; step = (224*4)%240 = 176.
        int xstart = (ptid * 4) % WW;

        for (int cam = 0; cam < NC; ++cam) {
            if (cam >= 2) BAR_SYNC(3 + (cam & 1));    // wait buffer free
            unsigned short* buf = su + (cam & 1) * SPAIRS;
            const float*  hm  = hmbase + (size_t)cam * camstride;
            const float4* hm4 = reinterpret_cast<const float4*>(hm);
            int x = xstart;
#pragma unroll 5
            for (int it = 0; it < PFILL_IT; ++it) {
                int q = ptid + it * PTHREADS;
                if (q < HMPIX / 4) {                  // warp-uniform (7680=224*34+64)
                    float4 v = __ldg(hm4 + q);
                    unsigned int qa = pack_u8x4(v);
                    unsigned int qn = __shfl_down_sync(0xffffffffu, qa, 1);
                    if (lane31 && x != WW - 4)
                        qn = __float2uint_rn(__ldg(hm + 4 * q + 4) * 255.f);
                    if (x == WW - 4) qn = 0u;         // col 240 OOB -> 0
                    uint2 st;
                    st.x = __byte_perm(qa, qn, 0x2110);   // (q0,q1, q1,q2)
                    st.y = __byte_perm(qa, qn, 0x4332);   // (q2,q3, q3,q4)
                    reinterpret_cast<uint2*>(buf)[q] = st;
                }
                x += 176; if (x >= WW) x -= WW;
            }
            BAR_ARRIVE(1 + (cam & 1));                // signal buffer full
        }
    } else {
        // ---------------- CONSUMER warps (25): gather only --------------
        float acc[BPT];
#pragma unroll
        for (int k = 0; k < BPT; ++k) acc[k] = 0.f;

        const __half2 BIAS = __half2half2(__ushort_as_half((unsigned short)0x6400));

        for (int cam = 0; cam < NC; ++cam) {
            BAR_SYNC(1 + (cam & 1));                  // wait buffer full
            const unsigned short* cur = su + (cam & 1) * SPAIRS;
            const uint2* __restrict__ rp = g_rec + cam * NB + base;

#pragma unroll
            for (int k = 0; k < BPT; ++k) {
                int i = k * CTHREADS + tid;
                uint2 r = __ldg(rp + i);
                unsigned int off = r.x & 0xFFFFu;
                __half2 t2  = __half2half2(__ushort_as_half((unsigned short)(r.x >> 16)));
                __half2 v01 = *reinterpret_cast<const __half2*>(&r.y);

                unsigned int a32 = (unsigned int)cur[off];        // LDS.U16 y0
                unsigned int b32 = (unsigned int)cur[off + WW];   // LDS.U16 y1
                unsigned int p0u = __byte_perm(a32, 0x64646464u, 0x4140);
                unsigned int p1u = __byte_perm(b32, 0x64646464u, 0x4140);
                __half2 p0b = *reinterpret_cast<const __half2*>(&p0u);
                __half2 p1b = *reinterpret_cast<const __half2*>(&p1u);
                __half2 d   = __hsub2(p1b, p0b);   // exact (biases cancel)
                __half2 p0  = __hsub2(p0b, BIAS);  // exact ints 0..255
                __half2 pl  = __hfma2(d, t2, p0);  // row lerp
                __half2 pr  = __hmul2(pl, v01);    // x weights (incl. 1/255)
                float2 f    = __half22float2(pr);
                acc[k] += f.x + f.y;               // fp32 accumulation
            }

            // Release the buffer for refill (only cams 0..2 get refilled+2).
            if (cam <= 2) BAR_ARRIVE(3 + (cam & 1));
        }

        float* o = out + ((size_t)(b * NJ + j)) * NB + base;
#pragma unroll
        for (int k = 0; k < BPT; ++k) {
            float v = acc[k] * 0.2f;                          // mean over 5 cams
            o[k * CTHREADS + tid] = fminf(fmaxf(v, 0.f), 1.f); // clip [0,1]
        }
    }
}

extern "C" void kernel_launch(void* const* d_in, const int* in_sizes, int n_in,
                              void* d_out, int out_size) {
    const float* heatmaps = (const float*)d_in[0];
    const float* grid     = (const float*)d_in[1];
    if (n_in >= 2 && in_sizes[0] == NC * NB * 2) {
        grid     = (const float*)d_in[0];
        heatmaps = (const float*)d_in[1];
    }

    const int smem_bytes = 2 * SPAIRS * (int)sizeof(unsigned short); // 123,840 B
    cudaFuncSetAttribute(sample_kernel,
                         cudaFuncAttributeMaxDynamicSharedMemorySize, smem_bytes);

    prep_kernel<<<(NC * NB / 2 + 255) / 256, 256>>>(grid);

    dim3 g(NCHUNK, NJ, BATCH);
    sample_kernel<<<g, THREADS, smem_bytes>>>(heatmaps, (float*)d_out);
}

// round 12
// speedup vs baseline: 2.0789x; 2.0789x over previous
#include <cuda_runtime.h>
#include <cuda_fp16.h>

// Problem constants
#define NC     5
#define NB     128000
#define BATCH  8
#define NJ     15
#define HH     128
#define WW     240
#define HMPIX  (HH*WW)        // 30720 pixels per (b,cam,j) heatmap

// Tiling: 1024 threads (32 warps). smem 122.9KB forces 1 CTA/SM.
// (Measured optimum across R1-R11; all structural departures were worse.)
#define THREADS 1024
#define BPT     25            // bins per thread
#define CHUNK   (THREADS*BPT) // 25600 bins per CTA
#define NCHUNK  (NB/CHUNK)    // 5 chunks -> grid 5 x 15 x 8 = 600 CTAs

// Fused 8-byte per-(cam,bin) record (shared across all b,j):
//   .x = off (bits 0..15) | t_half_bits (bits 16..31)
//   .y = half2(vA, vB)  -- x-weights, with border cases AND the u8 scale
//                          (1/255) folded in by prep.
// Gather semantics on the u8 corner-quad heatmap:
//   quad[off] = bytes (q00, q01, q10, q11) = round(255*hm) at
//               (y,x),(y,x+1),(y+1,x),(y+1,x+1); row y+1 / col x+1 OOB -> 0.
//   p0 = (q00,q01), p1 = (q10,q11) as exact halfs via 0x6400|q bias trick
//   result = (vA,vB) . ( p0 + t*(p1-p0) )
__device__ uint2 g_rec[NC*NB];

__device__ __forceinline__ uint2 make_record(float gx, float gy) {
    // align_corners=True mapping
    float ix = (gx + 1.0f) * 0.5f * (float)(WW - 1);
    float iy = (gy + 1.0f) * 0.5f * (float)(HH - 1);
    float x0f = floorf(ix), y0f = floorf(iy);
    float fx = ix - x0f,    fy = iy - y0f;
    int   x0 = (int)x0f,    y0 = (int)y0f;

    // x: quad at xc provides columns (xc, xc+1); fill zero-pads col xc+1 at
    // xc==WW-1, so an invalid x1 corner contributes 0 there.
    float wA, wB; int xc;
    if (x0 >= 0 && x0 < WW) { xc = x0; wA = 1.0f - fx; wB = fx;  }
    else if (x0 == -1)      { xc = 0;  wA = fx;        wB = 0.f; }
    else                    { xc = 0;  wA = 0.f;       wB = 0.f; }

    // y folded into (t, s): interior t=fy,s=1 (quads at y=127 have zero
    // bottom bytes, handling y1 OOB); y0==-1: row 0 only, s=fy; OOB: s=0.
    float t, s; int yc;
    if (y0 >= 0 && y0 < HH) { yc = y0; t = fy;  s = 1.f; }
    else if (y0 == -1)      { yc = 0;  t = 0.f; s = fy;  }
    else                    { yc = 0;  t = 0.f; s = 0.f; }

    unsigned int off = (unsigned int)(yc * WW + xc);   // <= 30719, 15 bits
    __half th = __float2half_rn(t);
    const float inv255 = 1.0f / 255.0f;
    __half2 v = __floats2half2_rn(wA * s * inv255, wB * s * inv255);

    uint2 r;
    r.x = off | ((unsigned int)__half_as_ushort(th) << 16);
    r.y = *reinterpret_cast<unsigned int*>(&v);
    return r;
}

__global__ void prep_kernel(const float* __restrict__ grid) {
    // Vectorized: each thread builds 2 records from one float4.
    int p = blockIdx.x * 256 + threadIdx.x;   // record pair index
    if (p >= NC * NB / 2) return;
    float4 g = reinterpret_cast<const float4*>(grid)[p];
    g_rec[p * 2]     = make_record(g.x, g.y);
    g_rec[p * 2 + 1] = make_record(g.z, g.w);
}

__device__ __forceinline__ unsigned int pack_u8x4(float4 v) {
    unsigned int q0 = __float2uint_rn(v.x * 255.f);
    unsigned int q1 = __float2uint_rn(v.y * 255.f);
    unsigned int q2 = __float2uint_rn(v.z * 255.f);
    unsigned int q3 = __float2uint_rn(v.w * 255.f);
    return q0 | (q1 << 8) | (q2 << 16) | (q3 << 24);
}

__global__ __launch_bounds__(THREADS, 1)
void sample_kernel(const float* __restrict__ heatmaps,
                   float* __restrict__ out) {
    // u8 corner-quad heatmap: HMPIX x uint32. 122,880 bytes.
    extern __shared__ unsigned int sq[];

    const int tid   = threadIdx.x;
    const int chunk = blockIdx.x;
    const int j     = blockIdx.y;
    const int b     = blockIdx.z;
    const int base  = chunk * CHUNK;

    // Fill coordinates: thread handles 4 consecutive pixels (one row) per
    // iteration. 240 % 4 == 0 -> a float4 never crosses a row.
    // Per-iteration step: p += 1024 -> +4096 pixels = 17 rows + 16 px.
    const int xstart = (tid * 4) % WW;     // first pixel's column
    const int ystart = tid / 60;           // first pixel's row (4*tid/240)

    float acc[BPT];
#pragma unroll
    for (int k = 0; k < BPT; ++k) acc[k] = 0.f;

    const __half2 BIAS = __half2half2(__ushort_as_half((unsigned short)0x6400));

    for (int cam = 0; cam < NC; ++cam) {
        __syncthreads();  // previous gathers done

        // Build u8 corner-quad heatmap in smem. Each thread: 2x LDG.128
        // (row y, row y+1), neighbor bytes via shfl, 1x STS.128 (4 quads).
        const float*  hm  = heatmaps + (((size_t)b * NC + cam) * NJ + j) * (size_t)HMPIX;
        const float4* hm4 = reinterpret_cast<const float4*>(hm);
        int x = xstart, y = ystart;
#pragma unroll
        for (int p = tid; p < HMPIX / 4; p += THREADS) {
            float4 a = __ldg(hm4 + p);
            bool has_b = (y < HH - 1);
            float4 bb = has_b ? __ldg(hm4 + p + WW / 4)
                              : make_float4(0.f, 0.f, 0.f, 0.f);

            unsigned int qa = pack_u8x4(a);
            unsigned int qb = pack_u8x4(bb);

            // Neighbor group's first bytes (pixel x+4 of rows y and y+1).
            unsigned int qa_n = __shfl_down_sync(0xffffffffu, qa, 1);
            unsigned int qb_n = __shfl_down_sync(0xffffffffu, qb, 1);
            if ((tid & 31) == 31 && x != WW - 4) {
                float a4 = __ldg(hm + 4 * p + 4);
                float b4 = has_b ? __ldg(hm + 4 * p + 4 + WW) : 0.f;
                qa_n = __float2uint_rn(a4 * 255.f);
                qb_n = __float2uint_rn(b4 * 255.f);
            }
            if (x == WW - 4) { qa_n = 0u; qb_n = 0u; }  // col 240 OOB -> 0

            // Shifted-by-one-byte rows: [a1,a2,a3,a4], [b1,b2,b3,b4]
            unsigned int qan = __byte_perm(qa, qa_n, 0x4321);
            unsigned int qbn = __byte_perm(qb, qb_n, 0x4321);

            // Interleave into quads: quad_i = (a_i, a_{i+1}, b_i, b_{i+1})
            unsigned int lo  = __byte_perm(qa,  qan, 0x5140);
            unsigned int lo2 = __byte_perm(qa,  qan, 0x7362);
            unsigned int hi  = __byte_perm(qb,  qbn, 0x5140);
            unsigned int hi2 = __byte_perm(qb,  qbn, 0x7362);
            uint4 st;
            st.x = __byte_perm(lo,  hi,  0x5410);  // (a0,a1, b0,b1)
            st.y = __byte_perm(lo,  hi,  0x7632);  // (a1,a2, b1,b2)
            st.z = __byte_perm(lo2, hi2, 0x5410);  // (a2,a3, b2,b3)
            st.w = __byte_perm(lo2, hi2, 0x7632);  // (a3,a4, b3,b4)
            *reinterpret_cast<uint4*>(sq + p * 4) = st;

            // advance (x,y): +4096 px = +17 rows +16 cols (wrap adds a row)
            x += 16; y += 17;
            if (x >= WW) { x -= WW; y += 1; }
        }
        __syncthreads();

        const uint2* __restrict__ rp = g_rec + cam * NB + base;

#pragma unroll
        for (int k = 0; k < BPT; ++k) {
            int i = k * THREADS + tid;
            uint2 r = __ldg(rp + i);
            unsigned int off = r.x & 0xFFFFu;
            // t2 = (t_half, t_half) in one PRMT (bytes 3,2 of r.x twice).
            unsigned int t2u = __byte_perm(r.x, r.x, 0x3232);
            __half2 t2  = *reinterpret_cast<const __half2*>(&t2u);
            __half2 v01 = *reinterpret_cast<const __half2*>(&r.y);

            unsigned int quad = sq[off];                       // 1x LDS.32
            unsigned int b01 = __byte_perm(quad, 0x64646464u, 0x4140);
            unsigned int b23 = __byte_perm(quad, 0x64646464u, 0x4342);
            __half2 p0b = *reinterpret_cast<const __half2*>(&b01);
            __half2 p1b = *reinterpret_cast<const __half2*>(&b23);
            __half2 d   = __hsub2(p1b, p0b);   // biases cancel; exact
            __half2 p0  = __hsub2(p0b, BIAS);  // exact integers 0..255
            __half2 pl  = __hfma2(d, t2, p0);  // row lerp
            __half2 pr  = __hmul2(pl, v01);    // x weights (incl. 1/255)
            float2 f    = __half22float2(pr);
            acc[k] += f.x + f.y;               // fp32 accumulation
        }
    }

    float* o = out + ((size_t)(b * NJ + j)) * NB + base;
#pragma unroll
    for (int k = 0; k < BPT; ++k) {
        float v = acc[k] * 0.2f;                          // mean over 5 cams
        o[k * THREADS + tid] = fminf(fmaxf(v, 0.f), 1.f); // clip [0,1]
    }
}

extern "C" void kernel_launch(void* const* d_in, const int* in_sizes, int n_in,
                              void* d_out, int out_size) {
    const float* heatmaps = (const float*)d_in[0];
    const float* grid     = (const float*)d_in[1];
    if (n_in >= 2 && in_sizes[0] == NC * NB * 2) {
        grid     = (const float*)d_in[0];
        heatmaps = (const float*)d_in[1];
    }

    const int smem_bytes = HMPIX * (int)sizeof(unsigned int);  // 122,880 B
    cudaFuncSetAttribute(sample_kernel,
                         cudaFuncAttributeMaxDynamicSharedMemorySize, smem_bytes);

    prep_kernel<<<(NC * NB / 2 + 255) / 256, 256>>>(grid);

    dim3 g(NCHUNK, NJ, BATCH);
    sample_kernel<<<g, THREADS, smem_bytes>>>(heatmaps, (float*)d_out);
}